// round 1
// baseline (speedup 1.0000x reference)
#include <cuda_runtime.h>
#include <math.h>

// ---------------- problem constants ----------------
#define TOKENS 200704          // 8*8*56*56
#define CD     128             // channels
#define NWIN   2048            // windows total (8 * 4*8*8)
#define NL     98              // tokens per window (2*7*7)
#define NHEAD  4
#define HD     32
#define SMEM_ATTN ((3*98*33 + 98*99) * 4)   // 77616 bytes

// ---------------- scratch (static device memory; no allocs allowed) -------
__device__ float g_xw  [(size_t)TOKENS * CD];       // LN1 + shift + window partition
__device__ float g_qkv [(size_t)TOKENS * 3 * CD];   // qkv gemm out
__device__ float g_bias[(size_t)NHEAD * NL * NL];   // materialized rel-pos bias
__device__ float g_attn[(size_t)TOKENS * CD];       // attention output (window layout)
__device__ float g_proj[(size_t)TOKENS * CD];       // proj gemm out (window layout)
__device__ float g_x2  [(size_t)TOKENS * CD];       // x + attn branch (spatial layout)
__device__ float g_y   [(size_t)TOKENS * CD];       // LN2 out
__device__ float g_hid [(size_t)TOKENS * 4 * CD];   // MLP hidden

// ---------------- rel-pos bias materialization ----------------
__global__ void bias_kernel(const float* __restrict__ rel_bias) {
    int t = blockIdx.x * blockDim.x + threadIdx.x;
    if (t >= NHEAD * NL * NL) return;
    int h = t / (NL * NL);
    int r = t % (NL * NL);
    int n = r / NL, m = r % NL;
    int id = n / 49, ih = (n / 7) % 7, iw = n % 7;
    int jd = m / 49, jh = (m / 7) % 7, jw = m % 7;
    int ridx = (id - jd + 1) * 169 + (ih - jh + 6) * 13 + (iw - jw + 6);
    g_bias[t] = rel_bias[ridx * NHEAD + h];
}

// ---------------- LN1 + cyclic shift + window partition (gather) ----------
// one warp per output token; 4 channels per lane (float4)
__global__ void ln1_kernel(const float* __restrict__ x,
                           const float* __restrict__ g, const float* __restrict__ b) {
    int warp = blockIdx.x * 8 + (threadIdx.x >> 5);
    int lane = threadIdx.x & 31;
    if (warp >= TOKENS) return;
    int tw  = warp;
    int win = tw / NL, n = tw % NL;
    int bb  = win >> 8;
    int wl  = win & 255;
    int dz = wl >> 6, hy = (wl >> 3) & 7, wx = wl & 7;
    int id = n / 49, ih = (n / 7) % 7, iw = n % 7;
    int d  = (dz * 2 + id + 1) & 7;                  // roll(-1) on D
    int hh = hy * 7 + ih + 3; if (hh >= 56) hh -= 56; // roll(-3) on H
    int ww = wx * 7 + iw + 3; if (ww >= 56) ww -= 56; // roll(-3) on W
    size_t src = ((((size_t)bb * 8 + d) * 56 + hh) * 56 + ww) * CD;

    float4 v = reinterpret_cast<const float4*>(x + src)[lane];
    float s1 = v.x + v.y + v.z + v.w;
    float s2 = v.x*v.x + v.y*v.y + v.z*v.z + v.w*v.w;
    #pragma unroll
    for (int o = 16; o; o >>= 1) {
        s1 += __shfl_xor_sync(0xffffffffu, s1, o);
        s2 += __shfl_xor_sync(0xffffffffu, s2, o);
    }
    float mean = s1 * (1.0f / 128.0f);
    float var  = s2 * (1.0f / 128.0f) - mean * mean;
    float inv  = rsqrtf(var + 1e-5f);
    float4 gg = reinterpret_cast<const float4*>(g)[lane];
    float4 bv = reinterpret_cast<const float4*>(b)[lane];
    float4 o;
    o.x = (v.x - mean) * inv * gg.x + bv.x;
    o.y = (v.y - mean) * inv * gg.y + bv.y;
    o.z = (v.z - mean) * inv * gg.z + bv.z;
    o.w = (v.w - mean) * inv * gg.w + bv.w;
    reinterpret_cast<float4*>(g_xw)[(size_t)tw * 32 + lane] = o;
}

// ---------------- LN2 (identity mapping, x2 -> y) ----------------
__global__ void ln2_kernel(const float* __restrict__ g, const float* __restrict__ b) {
    int warp = blockIdx.x * 8 + (threadIdx.x >> 5);
    int lane = threadIdx.x & 31;
    if (warp >= TOKENS) return;
    float4 v = reinterpret_cast<const float4*>(g_x2)[(size_t)warp * 32 + lane];
    float s1 = v.x + v.y + v.z + v.w;
    float s2 = v.x*v.x + v.y*v.y + v.z*v.z + v.w*v.w;
    #pragma unroll
    for (int o = 16; o; o >>= 1) {
        s1 += __shfl_xor_sync(0xffffffffu, s1, o);
        s2 += __shfl_xor_sync(0xffffffffu, s2, o);
    }
    float mean = s1 * (1.0f / 128.0f);
    float var  = s2 * (1.0f / 128.0f) - mean * mean;
    float inv  = rsqrtf(var + 1e-5f);
    float4 gg = reinterpret_cast<const float4*>(g)[lane];
    float4 bv = reinterpret_cast<const float4*>(b)[lane];
    float4 o;
    o.x = (v.x - mean) * inv * gg.x + bv.x;
    o.y = (v.y - mean) * inv * gg.y + bv.y;
    o.z = (v.z - mean) * inv * gg.z + bv.z;
    o.w = (v.w - mean) * inv * gg.w + bv.w;
    reinterpret_cast<float4*>(g_y)[(size_t)warp * 32 + lane] = o;
}

// ---------------- SGEMM: C(MxN) = A(MxK) @ W(NxK)^T + bias, epilogue MODE --
// MODE 0: bias only; MODE 1: bias + exact GELU; MODE 2: bias + residual add
// BM=BN=128, BK=8, 8x8 per thread, 256 threads. M%128==0, N%128==0, K%8==0.
template<int MODE>
__global__ void __launch_bounds__(256, 2)
sgemm128(const float* __restrict__ A, const float* __restrict__ W,
         const float* __restrict__ bias, const float* __restrict__ res,
         float* __restrict__ C, int M, int N, int K) {
    __shared__ float As[8][128];
    __shared__ float Bs[8][128];
    int tid = threadIdx.x;
    int m0 = blockIdx.y * 128, n0 = blockIdx.x * 128;
    int lr = tid >> 1;            // 0..127
    int lc = (tid & 1) * 4;       // 0 or 4
    const float* Ag = A + (size_t)(m0 + lr) * K + lc;
    const float* Bg = W + (size_t)(n0 + lr) * K + lc;
    int tx = tid & 15, ty = tid >> 4;

    float acc[8][8];
    #pragma unroll
    for (int i = 0; i < 8; i++)
        #pragma unroll
        for (int j = 0; j < 8; j++) acc[i][j] = 0.0f;

    for (int k0 = 0; k0 < K; k0 += 8) {
        float4 a = *reinterpret_cast<const float4*>(Ag + k0);
        float4 w4 = *reinterpret_cast<const float4*>(Bg + k0);
        As[lc + 0][lr] = a.x;  As[lc + 1][lr] = a.y;
        As[lc + 2][lr] = a.z;  As[lc + 3][lr] = a.w;
        Bs[lc + 0][lr] = w4.x; Bs[lc + 1][lr] = w4.y;
        Bs[lc + 2][lr] = w4.z; Bs[lc + 3][lr] = w4.w;
        __syncthreads();
        #pragma unroll
        for (int k = 0; k < 8; k++) {
            float4 a0 = *reinterpret_cast<float4*>(&As[k][ty * 8]);
            float4 a1 = *reinterpret_cast<float4*>(&As[k][ty * 8 + 4]);
            float4 b0 = *reinterpret_cast<float4*>(&Bs[k][tx * 8]);
            float4 b1 = *reinterpret_cast<float4*>(&Bs[k][tx * 8 + 4]);
            float am[8] = {a0.x, a0.y, a0.z, a0.w, a1.x, a1.y, a1.z, a1.w};
            float bn[8] = {b0.x, b0.y, b0.z, b0.w, b1.x, b1.y, b1.z, b1.w};
            #pragma unroll
            for (int i = 0; i < 8; i++)
                #pragma unroll
                for (int j = 0; j < 8; j++)
                    acc[i][j] += am[i] * bn[j];
        }
        __syncthreads();
    }

    #pragma unroll
    for (int i = 0; i < 8; i++) {
        int row = m0 + ty * 8 + i;
        #pragma unroll
        for (int j4 = 0; j4 < 2; j4++) {
            int col = n0 + tx * 8 + j4 * 4;
            float4 o;
            float* pv = &acc[i][j4 * 4];
            float v0 = pv[0] + bias[col + 0];
            float v1 = pv[1] + bias[col + 1];
            float v2 = pv[2] + bias[col + 2];
            float v3 = pv[3] + bias[col + 3];
            if (MODE == 1) {
                v0 = 0.5f * v0 * (1.0f + erff(v0 * 0.70710678118654752f));
                v1 = 0.5f * v1 * (1.0f + erff(v1 * 0.70710678118654752f));
                v2 = 0.5f * v2 * (1.0f + erff(v2 * 0.70710678118654752f));
                v3 = 0.5f * v3 * (1.0f + erff(v3 * 0.70710678118654752f));
            }
            if (MODE == 2) {
                const float4 r4 = *reinterpret_cast<const float4*>(res + (size_t)row * N + col);
                v0 += r4.x; v1 += r4.y; v2 += r4.z; v3 += r4.w;
            }
            o.x = v0; o.y = v1; o.z = v2; o.w = v3;
            *reinterpret_cast<float4*>(C + (size_t)row * N + col) = o;
        }
    }
}

// ---------------- windowed attention: one block per (window, head) --------
__global__ void attn_kernel(const float* __restrict__ mask) {
    extern __shared__ float sm[];
    float* qs = sm;                 // 98 x 33
    float* ks = qs + 98 * 33;       // 98 x 33
    float* vs = ks + 98 * 33;       // 98 x 33
    float* Ss = vs + 98 * 33;       // 98 x 99
    int win = blockIdx.x, h = blockIdx.y;
    int tid = threadIdx.x;
    const float* base = g_qkv + (size_t)win * NL * 384;

    for (int e = tid; e < NL * 32; e += 256) {
        int n = e >> 5, d = e & 31;
        const float* row = base + (size_t)n * 384 + h * 32 + d;
        qs[n * 33 + d] = row[0]   * 0.17677669529663689f;  // 1/sqrt(32)
        ks[n * 33 + d] = row[128];
        vs[n * 33 + d] = row[256];
    }
    __syncthreads();

    int widx = win & 255;
    const float* mrow = mask + (size_t)widx * NL * NL;
    const float* brow = g_bias + (size_t)h * NL * NL;
    for (int e = tid; e < NL * NL; e += 256) {
        int n = e / NL, m = e % NL;
        float s = 0.0f;
        #pragma unroll
        for (int d = 0; d < 32; d++) s += qs[n * 33 + d] * ks[m * 33 + d];
        Ss[n * 99 + m] = s + brow[e] + mrow[e];
    }
    __syncthreads();

    int warp = tid >> 5, lane = tid & 31;
    for (int n = warp; n < NL; n += 8) {
        float v0 = Ss[n * 99 + lane];
        float v1 = Ss[n * 99 + lane + 32];
        float v2 = Ss[n * 99 + lane + 64];
        float v3 = (lane + 96 < NL) ? Ss[n * 99 + lane + 96] : -3.0e38f;
        float mx = fmaxf(fmaxf(v0, v1), fmaxf(v2, v3));
        #pragma unroll
        for (int o = 16; o; o >>= 1) mx = fmaxf(mx, __shfl_xor_sync(0xffffffffu, mx, o));
        v0 = __expf(v0 - mx); v1 = __expf(v1 - mx); v2 = __expf(v2 - mx);
        v3 = (lane + 96 < NL) ? __expf(v3 - mx) : 0.0f;
        float sum = v0 + v1 + v2 + v3;
        #pragma unroll
        for (int o = 16; o; o >>= 1) sum += __shfl_xor_sync(0xffffffffu, sum, o);
        float r = 1.0f / sum;
        Ss[n * 99 + lane]      = v0 * r;
        Ss[n * 99 + lane + 32] = v1 * r;
        Ss[n * 99 + lane + 64] = v2 * r;
        if (lane + 96 < NL) Ss[n * 99 + lane + 96] = v3 * r;
    }
    __syncthreads();

    for (int e = tid; e < NL * 32; e += 256) {
        int n = e >> 5, d = e & 31;
        float s = 0.0f;
        #pragma unroll 7
        for (int m = 0; m < NL; m++) s += Ss[n * 99 + m] * vs[m * 33 + d];
        g_attn[((size_t)win * NL + n) * CD + h * 32 + d] = s;
    }
}

// ---------------- window reverse + roll + residual add -> x2 --------------
__global__ void residual_kernel(const float* __restrict__ x) {
    size_t idx = (size_t)blockIdx.x * 256 + threadIdx.x;   // over TOKENS*32 float4
    if (idx >= (size_t)TOKENS * 32) return;
    int t  = (int)(idx >> 5);
    int c4 = (int)(idx & 31);
    int w  = t % 56;
    int hh = (t / 56) % 56;
    int d  = (t / 3136) % 8;
    int bb = t / 25088;
    int ds = (d + 7) & 7;
    int hs = hh - 3; if (hs < 0) hs += 56;
    int ws = w  - 3; if (ws < 0) ws += 56;
    int win = bb * 256 + (ds >> 1) * 64 + (hs / 7) * 8 + (ws / 7);
    int n   = (ds & 1) * 49 + (hs % 7) * 7 + (ws % 7);
    float4 p  = reinterpret_cast<const float4*>(g_proj)[((size_t)win * NL + n) * 32 + c4];
    float4 xv = reinterpret_cast<const float4*>(x)[idx];
    float4 o;
    o.x = xv.x + p.x; o.y = xv.y + p.y; o.z = xv.z + p.z; o.w = xv.w + p.w;
    reinterpret_cast<float4*>(g_x2)[idx] = o;
}

// ---------------- launch ----------------
extern "C" void kernel_launch(void* const* d_in, const int* in_sizes, int n_in,
                              void* d_out, int out_size) {
    const float* x     = (const float*)d_in[0];
    const float* mask  = (const float*)d_in[1];
    const float* n1g   = (const float*)d_in[2];
    const float* n1b   = (const float*)d_in[3];
    const float* qkvw  = (const float*)d_in[4];
    const float* qkvb  = (const float*)d_in[5];
    const float* relb  = (const float*)d_in[6];
    const float* projw = (const float*)d_in[7];
    const float* projb = (const float*)d_in[8];
    const float* n2g   = (const float*)d_in[9];
    const float* n2b   = (const float*)d_in[10];
    const float* fc1w  = (const float*)d_in[11];
    const float* fc1b  = (const float*)d_in[12];
    const float* fc2w  = (const float*)d_in[13];
    const float* fc2b  = (const float*)d_in[14];
    float* out = (float*)d_out;

    void *p_xw, *p_qkv, *p_attn, *p_proj, *p_x2, *p_y, *p_hid;
    cudaGetSymbolAddress(&p_xw,   g_xw);
    cudaGetSymbolAddress(&p_qkv,  g_qkv);
    cudaGetSymbolAddress(&p_attn, g_attn);
    cudaGetSymbolAddress(&p_proj, g_proj);
    cudaGetSymbolAddress(&p_x2,   g_x2);
    cudaGetSymbolAddress(&p_y,    g_y);
    cudaGetSymbolAddress(&p_hid,  g_hid);

    cudaFuncSetAttribute(attn_kernel, cudaFuncAttributeMaxDynamicSharedMemorySize, SMEM_ATTN);

    // 1. rel-pos bias table -> (4, 98, 98)
    bias_kernel<<<(NHEAD * NL * NL + 255) / 256, 256>>>(relb);
    // 2. LN1 + shift + window partition
    ln1_kernel<<<TOKENS / 8, 256>>>(x, n1g, n1b);
    // 3. QKV gemm: (200704,128)@(128,384)
    sgemm128<0><<<dim3(3, TOKENS / 128), 256>>>((const float*)p_xw, qkvw, qkvb, nullptr,
                                                (float*)p_qkv, TOKENS, 384, 128);
    // 4. windowed attention
    attn_kernel<<<dim3(NWIN, NHEAD), 256, SMEM_ATTN>>>(mask);
    // 5. proj gemm
    sgemm128<0><<<dim3(1, TOKENS / 128), 256>>>((const float*)p_attn, projw, projb, nullptr,
                                                (float*)p_proj, TOKENS, 128, 128);
    // 6. window reverse + roll + residual
    residual_kernel<<<(TOKENS * 32) / 256, 256>>>(x);
    // 7. LN2
    ln2_kernel<<<TOKENS / 8, 256>>>(n2g, n2b);
    // 8. fc1 + GELU
    sgemm128<1><<<dim3(4, TOKENS / 128), 256>>>((const float*)p_y, fc1w, fc1b, nullptr,
                                                (float*)p_hid, TOKENS, 512, 128);
    // 9. fc2 + residual -> out
    sgemm128<2><<<dim3(1, TOKENS / 128), 256>>>((const float*)p_hid, fc2w, fc2b,
                                                (const float*)p_x2, out, TOKENS, 128, 512);
}

// round 3
// speedup vs baseline: 1.8771x; 1.8771x over previous
#include <cuda_runtime.h>
#include <math.h>
#include <stdint.h>

// ---------------- problem constants ----------------
#define TOKENS 200704          // 8*8*56*56
#define CD     128             // channels
#define NWIN   2048            // windows total (8 * 4*8*8)
#define NL     98              // tokens per window (2*7*7)
#define NHEAD  4

// attention smem: qs 98x32, kt 32x100, vs 98x32, Ss 100x100
#define ATTN_SMEM ((98*32 + 32*100 + 98*32 + 100*100) * 4)

// ---------------- scratch (static device memory; no allocs allowed) -------
__device__ float g_xw  [(size_t)TOKENS * CD];       // LN1 + shift + window partition
__device__ float g_qkv [(size_t)TOKENS * 3 * CD];   // qkv gemm out
__device__ float g_bias[(size_t)NHEAD * NL * NL];   // materialized rel-pos bias
__device__ float g_attn[(size_t)TOKENS * CD];       // attention output (window layout)
__device__ float g_proj[(size_t)TOKENS * CD];       // proj gemm out (window layout)
__device__ float g_x2  [(size_t)TOKENS * CD];       // x + attn branch (spatial layout)
__device__ float g_y   [(size_t)TOKENS * CD];       // LN2 out
__device__ float g_hid [(size_t)TOKENS * 4 * CD];   // MLP hidden

// ---------------- tf32 helpers ----------------
__device__ __forceinline__ uint32_t f2tf32(float v) {
    uint32_t o;
    asm("cvt.rna.tf32.f32 %0, %1;" : "=r"(o) : "f"(v));
    return o;
}
__device__ __forceinline__ void mma_tf32(float c[4],
                                         uint32_t a0, uint32_t a1, uint32_t a2, uint32_t a3,
                                         uint32_t b0, uint32_t b1) {
    asm volatile(
        "mma.sync.aligned.m16n8k8.row.col.f32.tf32.tf32.f32 "
        "{%0,%1,%2,%3}, {%4,%5,%6,%7}, {%8,%9}, {%0,%1,%2,%3};\n"
        : "+f"(c[0]), "+f"(c[1]), "+f"(c[2]), "+f"(c[3])
        : "r"(a0), "r"(a1), "r"(a2), "r"(a3), "r"(b0), "r"(b1));
}

// ================= tensor-core GEMM: C(MxN) = A(MxK) @ W(NxK)^T + epilogue
// block 128x128, BK=32, 8 warps (2 m x 4 n), warp tile 64x32 (4x4 m16n8k8)
// MODE 0: +bias; MODE 1: +bias, GELU; MODE 2: +bias, +residual
template<int MODE>
__global__ void __launch_bounds__(256, 2)
mma_gemm(const float* __restrict__ A, const float* __restrict__ W,
         const float* __restrict__ bias, const float* __restrict__ res,
         float* __restrict__ C, int K, int N) {
    __shared__ uint32_t As[128][32];
    __shared__ uint32_t Bs[128][32];
    int tid = threadIdx.x;
    int wid = tid >> 5, lane = tid & 31;
    int g = lane >> 2, cc = lane & 3;
    int m0 = blockIdx.y * 128, n0 = blockIdx.x * 128;
    int wm = wid & 1, wn = wid >> 1;          // 2 x 4 warp grid

    float acc[4][4][4];
    #pragma unroll
    for (int i = 0; i < 4; i++)
        #pragma unroll
        for (int j = 0; j < 4; j++)
            #pragma unroll
            for (int t = 0; t < 4; t++) acc[i][j][t] = 0.0f;

    for (int kchunk = 0; kchunk < K; kchunk += 32) {
        // load A (128x32) and W (128x32), cvt to tf32, swizzled store
        #pragma unroll
        for (int i = 0; i < 4; i++) {
            int idx = tid + i * 256;
            int r = idx >> 3, c4 = idx & 7;
            int sc = (c4 * 4) ^ ((r & 7) * 4);
            float4 va = *reinterpret_cast<const float4*>(A + (size_t)(m0 + r) * K + kchunk + c4 * 4);
            uint4 ta;
            ta.x = f2tf32(va.x); ta.y = f2tf32(va.y);
            ta.z = f2tf32(va.z); ta.w = f2tf32(va.w);
            *reinterpret_cast<uint4*>(&As[r][sc]) = ta;
            float4 vb = *reinterpret_cast<const float4*>(W + (size_t)(n0 + r) * K + kchunk + c4 * 4);
            uint4 tb;
            tb.x = f2tf32(vb.x); tb.y = f2tf32(vb.y);
            tb.z = f2tf32(vb.z); tb.w = f2tf32(vb.w);
            *reinterpret_cast<uint4*>(&Bs[r][sc]) = tb;
        }
        __syncthreads();

        #pragma unroll
        for (int ks = 0; ks < 4; ks++) {
            int k0 = ks * 8;
            int sw = g * 4;
            uint32_t af[4][4];
            #pragma unroll
            for (int mt = 0; mt < 4; mt++) {
                int rb = wm * 64 + mt * 16 + g;
                af[mt][0] = As[rb    ][(k0 + cc)     ^ sw];
                af[mt][1] = As[rb + 8][(k0 + cc)     ^ sw];
                af[mt][2] = As[rb    ][(k0 + cc + 4) ^ sw];
                af[mt][3] = As[rb + 8][(k0 + cc + 4) ^ sw];
            }
            uint32_t bf[4][2];
            #pragma unroll
            for (int nt = 0; nt < 4; nt++) {
                int nb = wn * 32 + nt * 8 + g;
                bf[nt][0] = Bs[nb][(k0 + cc)     ^ sw];
                bf[nt][1] = Bs[nb][(k0 + cc + 4) ^ sw];
            }
            #pragma unroll
            for (int mt = 0; mt < 4; mt++)
                #pragma unroll
                for (int nt = 0; nt < 4; nt++)
                    mma_tf32(acc[mt][nt], af[mt][0], af[mt][1], af[mt][2], af[mt][3],
                             bf[nt][0], bf[nt][1]);
        }
        __syncthreads();
    }

    // epilogue
    #pragma unroll
    for (int mt = 0; mt < 4; mt++) {
        int r0 = m0 + wm * 64 + mt * 16 + g;
        #pragma unroll
        for (int nt = 0; nt < 4; nt++) {
            int cb = n0 + wn * 32 + nt * 8 + cc * 2;
            float2 bb = *reinterpret_cast<const float2*>(bias + cb);
            #pragma unroll
            for (int hrow = 0; hrow < 2; hrow++) {
                int row = r0 + hrow * 8;
                float v0 = acc[mt][nt][hrow * 2 + 0] + bb.x;
                float v1 = acc[mt][nt][hrow * 2 + 1] + bb.y;
                if (MODE == 1) {
                    v0 = 0.5f * v0 * (1.0f + erff(v0 * 0.70710678118654752f));
                    v1 = 0.5f * v1 * (1.0f + erff(v1 * 0.70710678118654752f));
                }
                if (MODE == 2) {
                    float2 r2 = *reinterpret_cast<const float2*>(res + (size_t)row * N + cb);
                    v0 += r2.x; v1 += r2.y;
                }
                float2 o; o.x = v0; o.y = v1;
                *reinterpret_cast<float2*>(C + (size_t)row * N + cb) = o;
            }
        }
    }
}

// ---------------- rel-pos bias materialization ----------------
__global__ void bias_kernel(const float* __restrict__ rel_bias) {
    int t = blockIdx.x * blockDim.x + threadIdx.x;
    if (t >= NHEAD * NL * NL) return;
    int h = t / (NL * NL);
    int r = t % (NL * NL);
    int n = r / NL, m = r % NL;
    int id = n / 49, ih = (n / 7) % 7, iw = n % 7;
    int jd = m / 49, jh = (m / 7) % 7, jw = m % 7;
    int ridx = (id - jd + 1) * 169 + (ih - jh + 6) * 13 + (iw - jw + 6);
    g_bias[t] = rel_bias[ridx * NHEAD + h];
}

// ---------------- LN1 + cyclic shift + window partition (gather) ----------
__global__ void ln1_kernel(const float* __restrict__ x,
                           const float* __restrict__ g, const float* __restrict__ b) {
    int warp = blockIdx.x * 8 + (threadIdx.x >> 5);
    int lane = threadIdx.x & 31;
    if (warp >= TOKENS) return;
    int win = warp / NL, n = warp % NL;
    int bb  = win >> 8;
    int wl  = win & 255;
    int dz = wl >> 6, hy = (wl >> 3) & 7, wx = wl & 7;
    int id = n / 49, ih = (n / 7) % 7, iw = n % 7;
    int d  = (dz * 2 + id + 1) & 7;
    int hh = hy * 7 + ih + 3; if (hh >= 56) hh -= 56;
    int ww = wx * 7 + iw + 3; if (ww >= 56) ww -= 56;
    size_t src = ((((size_t)bb * 8 + d) * 56 + hh) * 56 + ww) * CD;

    float4 v = reinterpret_cast<const float4*>(x + src)[lane];
    float s1 = v.x + v.y + v.z + v.w;
    float s2 = v.x*v.x + v.y*v.y + v.z*v.z + v.w*v.w;
    #pragma unroll
    for (int o = 16; o; o >>= 1) {
        s1 += __shfl_xor_sync(0xffffffffu, s1, o);
        s2 += __shfl_xor_sync(0xffffffffu, s2, o);
    }
    float mean = s1 * (1.0f / 128.0f);
    float var  = s2 * (1.0f / 128.0f) - mean * mean;
    float inv  = rsqrtf(var + 1e-5f);
    float4 gg = reinterpret_cast<const float4*>(g)[lane];
    float4 bv = reinterpret_cast<const float4*>(b)[lane];
    float4 o;
    o.x = (v.x - mean) * inv * gg.x + bv.x;
    o.y = (v.y - mean) * inv * gg.y + bv.y;
    o.z = (v.z - mean) * inv * gg.z + bv.z;
    o.w = (v.w - mean) * inv * gg.w + bv.w;
    reinterpret_cast<float4*>(g_xw)[(size_t)warp * 32 + lane] = o;
}

// ---------------- LN2 ----------------
__global__ void ln2_kernel(const float* __restrict__ g, const float* __restrict__ b) {
    int warp = blockIdx.x * 8 + (threadIdx.x >> 5);
    int lane = threadIdx.x & 31;
    if (warp >= TOKENS) return;
    float4 v = reinterpret_cast<const float4*>(g_x2)[(size_t)warp * 32 + lane];
    float s1 = v.x + v.y + v.z + v.w;
    float s2 = v.x*v.x + v.y*v.y + v.z*v.z + v.w*v.w;
    #pragma unroll
    for (int o = 16; o; o >>= 1) {
        s1 += __shfl_xor_sync(0xffffffffu, s1, o);
        s2 += __shfl_xor_sync(0xffffffffu, s2, o);
    }
    float mean = s1 * (1.0f / 128.0f);
    float var  = s2 * (1.0f / 128.0f) - mean * mean;
    float inv  = rsqrtf(var + 1e-5f);
    float4 gg = reinterpret_cast<const float4*>(g)[lane];
    float4 bv = reinterpret_cast<const float4*>(b)[lane];
    float4 o;
    o.x = (v.x - mean) * inv * gg.x + bv.x;
    o.y = (v.y - mean) * inv * gg.y + bv.y;
    o.z = (v.z - mean) * inv * gg.z + bv.z;
    o.w = (v.w - mean) * inv * gg.w + bv.w;
    reinterpret_cast<float4*>(g_y)[(size_t)warp * 32 + lane] = o;
}

// ---------------- windowed attention: one block per (window, head) --------
__global__ void attn_kernel(const float* __restrict__ mask) {
    extern __shared__ float smf[];
    float* qs = smf;                 // [98][32]
    float* kt = qs + 98 * 32;        // [32][100] (d-major, m padded to 100)
    float* vs = kt + 32 * 100;       // [98][32]
    float* Ss = vs + 98 * 32;        // [100][100]
    int win = blockIdx.x, h = blockIdx.y;
    int tid = threadIdx.x, wid = tid >> 5, lane = tid & 31;
    const float* base = g_qkv + (size_t)win * NL * 384 + h * 32;

    if (tid < 64) kt[(tid >> 1) * 100 + 98 + (tid & 1)] = 0.0f;
    for (int e = tid; e < NL * 32; e += 256) {
        int n = e >> 5, d = e & 31;
        const float* row = base + (size_t)n * 384 + d;
        qs[e] = row[0] * 0.17677669529663689f;   // 1/sqrt(32)
        kt[d * 100 + n] = row[128];
        vs[e] = row[256];
    }
    __syncthreads();

    const float* mrow = mask + (size_t)(win & 255) * NL * NL;
    const float* brow = g_bias + (size_t)h * NL * NL;
    int m0 = lane * 4;
    for (int n = wid; n < NL; n += 8) {
        float s0 = 0, s1 = 0, s2 = 0, s3 = 0;
        #pragma unroll 8
        for (int d = 0; d < 32; d++) {
            float qv = qs[n * 32 + d];
            float4 kv = *reinterpret_cast<const float4*>(kt + d * 100 + m0);
            s0 += qv * kv.x; s1 += qv * kv.y; s2 += qv * kv.z; s3 += qv * kv.w;
        }
        if (m0 + 0 < NL) s0 += brow[n * NL + m0 + 0] + mrow[n * NL + m0 + 0]; else s0 = -3.0e38f;
        if (m0 + 1 < NL) s1 += brow[n * NL + m0 + 1] + mrow[n * NL + m0 + 1]; else s1 = -3.0e38f;
        if (m0 + 2 < NL) s2 += brow[n * NL + m0 + 2] + mrow[n * NL + m0 + 2]; else s2 = -3.0e38f;
        if (m0 + 3 < NL) s3 += brow[n * NL + m0 + 3] + mrow[n * NL + m0 + 3]; else s3 = -3.0e38f;
        float mx = fmaxf(fmaxf(s0, s1), fmaxf(s2, s3));
        #pragma unroll
        for (int o = 16; o; o >>= 1) mx = fmaxf(mx, __shfl_xor_sync(0xffffffffu, mx, o));
        s0 = __expf(s0 - mx); s1 = __expf(s1 - mx);
        s2 = __expf(s2 - mx); s3 = __expf(s3 - mx);
        float sum = s0 + s1 + s2 + s3;
        #pragma unroll
        for (int o = 16; o; o >>= 1) sum += __shfl_xor_sync(0xffffffffu, sum, o);
        float r = 1.0f / sum;
        if (m0 < 100) {
            float4 w; w.x = s0 * r; w.y = s1 * r; w.z = s2 * r; w.w = s3 * r;
            *reinterpret_cast<float4*>(Ss + n * 100 + m0) = w;
        }
    }
    __syncthreads();

    float* outb = g_attn + (size_t)win * NL * CD + h * 32 + lane;
    for (int nq = wid; nq < 25; nq += 8) {
        int n0 = nq * 4;
        float a0 = 0, a1 = 0, a2 = 0, a3 = 0;
        #pragma unroll 7
        for (int m = 0; m < NL; m++) {
            float v = vs[m * 32 + lane];
            a0 += Ss[(n0 + 0) * 100 + m] * v;
            a1 += Ss[(n0 + 1) * 100 + m] * v;
            a2 += Ss[(n0 + 2) * 100 + m] * v;
            a3 += Ss[(n0 + 3) * 100 + m] * v;
        }
        outb[(size_t)(n0 + 0) * CD] = a0;
        if (n0 + 1 < NL) outb[(size_t)(n0 + 1) * CD] = a1;
        if (n0 + 2 < NL) outb[(size_t)(n0 + 2) * CD] = a2;
        if (n0 + 3 < NL) outb[(size_t)(n0 + 3) * CD] = a3;
    }
}

// ---------------- window reverse + roll + residual add -> x2 --------------
__global__ void residual_kernel(const float* __restrict__ x) {
    size_t idx = (size_t)blockIdx.x * 256 + threadIdx.x;   // over TOKENS*32 float4
    if (idx >= (size_t)TOKENS * 32) return;
    int t  = (int)(idx >> 5);
    int c4 = (int)(idx & 31);
    int w  = t % 56;
    int hh = (t / 56) % 56;
    int d  = (t / 3136) % 8;
    int bb = t / 25088;
    int ds = (d + 7) & 7;
    int hs = hh - 3; if (hs < 0) hs += 56;
    int ws = w  - 3; if (ws < 0) ws += 56;
    int win = bb * 256 + (ds >> 1) * 64 + (hs / 7) * 8 + (ws / 7);
    int n   = (ds & 1) * 49 + (hs % 7) * 7 + (ws % 7);
    float4 p  = reinterpret_cast<const float4*>(g_proj)[((size_t)win * NL + n) * 32 + c4];
    float4 xv = reinterpret_cast<const float4*>(x)[idx];
    float4 o;
    o.x = xv.x + p.x; o.y = xv.y + p.y; o.z = xv.z + p.z; o.w = xv.w + p.w;
    reinterpret_cast<float4*>(g_x2)[idx] = o;
}

// ---------------- launch ----------------
extern "C" void kernel_launch(void* const* d_in, const int* in_sizes, int n_in,
                              void* d_out, int out_size) {
    const float* x     = (const float*)d_in[0];
    const float* mask  = (const float*)d_in[1];
    const float* n1g   = (const float*)d_in[2];
    const float* n1b   = (const float*)d_in[3];
    const float* qkvw  = (const float*)d_in[4];
    const float* qkvb  = (const float*)d_in[5];
    const float* relb  = (const float*)d_in[6];
    const float* projw = (const float*)d_in[7];
    const float* projb = (const float*)d_in[8];
    const float* n2g   = (const float*)d_in[9];
    const float* n2b   = (const float*)d_in[10];
    const float* fc1w  = (const float*)d_in[11];
    const float* fc1b  = (const float*)d_in[12];
    const float* fc2w  = (const float*)d_in[13];
    const float* fc2b  = (const float*)d_in[14];
    float* out = (float*)d_out;

    void *p_xw, *p_qkv, *p_attn, *p_proj, *p_x2, *p_y, *p_hid;
    cudaGetSymbolAddress(&p_xw,   g_xw);
    cudaGetSymbolAddress(&p_qkv,  g_qkv);
    cudaGetSymbolAddress(&p_attn, g_attn);
    cudaGetSymbolAddress(&p_proj, g_proj);
    cudaGetSymbolAddress(&p_x2,   g_x2);
    cudaGetSymbolAddress(&p_y,    g_y);
    cudaGetSymbolAddress(&p_hid,  g_hid);

    cudaFuncSetAttribute(attn_kernel, cudaFuncAttributeMaxDynamicSharedMemorySize, ATTN_SMEM);

    // 1. rel-pos bias table
    bias_kernel<<<(NHEAD * NL * NL + 255) / 256, 256>>>(relb);
    // 2. LN1 + shift + window partition
    ln1_kernel<<<TOKENS / 8, 256>>>(x, n1g, n1b);
    // 3. QKV gemm (tf32 tensor cores)
    mma_gemm<0><<<dim3(3, TOKENS / 128), 256>>>(
        (const float*)p_xw, qkvw, qkvb, nullptr, (float*)p_qkv, 128, 384);
    // 4. windowed attention
    attn_kernel<<<dim3(NWIN, NHEAD), 256, ATTN_SMEM>>>(mask);
    // 5. proj gemm
    mma_gemm<0><<<dim3(1, TOKENS / 128), 256>>>(
        (const float*)p_attn, projw, projb, nullptr, (float*)p_proj, 128, 128);
    // 6. window reverse + roll + residual
    residual_kernel<<<(TOKENS * 32) / 256, 256>>>(x);
    // 7. LN2
    ln2_kernel<<<TOKENS / 8, 256>>>(n2g, n2b);
    // 8. fc1 + GELU
    mma_gemm<1><<<dim3(4, TOKENS / 128), 256>>>(
        (const float*)p_y, fc1w, fc1b, nullptr, (float*)p_hid, 128, 512);
    // 9. fc2 + residual -> out
    mma_gemm<2><<<dim3(1, TOKENS / 128), 256>>>(
        (const float*)p_hid, fc2w, fc2b, (const float*)p_x2, out, 512, 128);
}

// round 4
// speedup vs baseline: 2.6112x; 1.3910x over previous
#include <cuda_runtime.h>
#include <math.h>
#include <stdint.h>

// ---------------- problem constants ----------------
#define TOKENS 200704          // 8*8*56*56
#define CD     128             // channels
#define NWIN   2048            // windows total (8 * 4*8*8)
#define NL     98              // tokens per window (2*7*7)
#define NHEAD  4

// tc attention smem: Q[112][32] K[104][32] V[104][32] S[112][108]
#define AT_PITCH 108
#define ATTN_SMEM ((112*32 + 104*32 + 104*32 + 112*AT_PITCH) * 4)

// ---------------- scratch (static device memory; no allocs allowed) -------
__device__ float g_xw  [(size_t)TOKENS * CD];
__device__ float g_qkv [(size_t)TOKENS * 3 * CD];
__device__ float g_bias[(size_t)NHEAD * NL * NL];
__device__ float g_attn[(size_t)TOKENS * CD];
__device__ float g_proj[(size_t)TOKENS * CD];
__device__ float g_x2  [(size_t)TOKENS * CD];
__device__ float g_y   [(size_t)TOKENS * CD];
__device__ float g_hid [(size_t)TOKENS * 4 * CD];

// ---------------- tf32 helpers ----------------
__device__ __forceinline__ uint32_t f2tf32(float v) {
    uint32_t o;
    asm("cvt.rna.tf32.f32 %0, %1;" : "=r"(o) : "f"(v));
    return o;
}
__device__ __forceinline__ float tf32r(float v) {
    uint32_t o;
    asm("cvt.rna.tf32.f32 %0, %1;" : "=r"(o) : "f"(v));
    return __uint_as_float(o);
}
__device__ __forceinline__ void mma_tf32(float c[4],
                                         uint32_t a0, uint32_t a1, uint32_t a2, uint32_t a3,
                                         uint32_t b0, uint32_t b1) {
    asm volatile(
        "mma.sync.aligned.m16n8k8.row.col.f32.tf32.tf32.f32 "
        "{%0,%1,%2,%3}, {%4,%5,%6,%7}, {%8,%9}, {%0,%1,%2,%3};\n"
        : "+f"(c[0]), "+f"(c[1]), "+f"(c[2]), "+f"(c[3])
        : "r"(a0), "r"(a1), "r"(a2), "r"(a3), "r"(b0), "r"(b1));
}

// ================= tensor-core GEMM (unchanged from R3) ====================
template<int MODE>
__global__ void __launch_bounds__(256, 2)
mma_gemm(const float* __restrict__ A, const float* __restrict__ W,
         const float* __restrict__ bias, const float* __restrict__ res,
         float* __restrict__ C, int K, int N) {
    __shared__ uint32_t As[128][32];
    __shared__ uint32_t Bs[128][32];
    int tid = threadIdx.x;
    int wid = tid >> 5, lane = tid & 31;
    int g = lane >> 2, cc = lane & 3;
    int m0 = blockIdx.y * 128, n0 = blockIdx.x * 128;
    int wm = wid & 1, wn = wid >> 1;

    float acc[4][4][4];
    #pragma unroll
    for (int i = 0; i < 4; i++)
        #pragma unroll
        for (int j = 0; j < 4; j++)
            #pragma unroll
            for (int t = 0; t < 4; t++) acc[i][j][t] = 0.0f;

    for (int kchunk = 0; kchunk < K; kchunk += 32) {
        #pragma unroll
        for (int i = 0; i < 4; i++) {
            int idx = tid + i * 256;
            int r = idx >> 3, c4 = idx & 7;
            int sc = (c4 * 4) ^ ((r & 7) * 4);
            float4 va = *reinterpret_cast<const float4*>(A + (size_t)(m0 + r) * K + kchunk + c4 * 4);
            uint4 ta;
            ta.x = f2tf32(va.x); ta.y = f2tf32(va.y);
            ta.z = f2tf32(va.z); ta.w = f2tf32(va.w);
            *reinterpret_cast<uint4*>(&As[r][sc]) = ta;
            float4 vb = *reinterpret_cast<const float4*>(W + (size_t)(n0 + r) * K + kchunk + c4 * 4);
            uint4 tb;
            tb.x = f2tf32(vb.x); tb.y = f2tf32(vb.y);
            tb.z = f2tf32(vb.z); tb.w = f2tf32(vb.w);
            *reinterpret_cast<uint4*>(&Bs[r][sc]) = tb;
        }
        __syncthreads();

        #pragma unroll
        for (int ks = 0; ks < 4; ks++) {
            int k0 = ks * 8;
            int sw = g * 4;
            uint32_t af[4][4];
            #pragma unroll
            for (int mt = 0; mt < 4; mt++) {
                int rb = wm * 64 + mt * 16 + g;
                af[mt][0] = As[rb    ][(k0 + cc)     ^ sw];
                af[mt][1] = As[rb + 8][(k0 + cc)     ^ sw];
                af[mt][2] = As[rb    ][(k0 + cc + 4) ^ sw];
                af[mt][3] = As[rb + 8][(k0 + cc + 4) ^ sw];
            }
            uint32_t bf[4][2];
            #pragma unroll
            for (int nt = 0; nt < 4; nt++) {
                int nb = wn * 32 + nt * 8 + g;
                bf[nt][0] = Bs[nb][(k0 + cc)     ^ sw];
                bf[nt][1] = Bs[nb][(k0 + cc + 4) ^ sw];
            }
            #pragma unroll
            for (int mt = 0; mt < 4; mt++)
                #pragma unroll
                for (int nt = 0; nt < 4; nt++)
                    mma_tf32(acc[mt][nt], af[mt][0], af[mt][1], af[mt][2], af[mt][3],
                             bf[nt][0], bf[nt][1]);
        }
        __syncthreads();
    }

    #pragma unroll
    for (int mt = 0; mt < 4; mt++) {
        int r0 = m0 + wm * 64 + mt * 16 + g;
        #pragma unroll
        for (int nt = 0; nt < 4; nt++) {
            int cb = n0 + wn * 32 + nt * 8 + cc * 2;
            float2 bb = *reinterpret_cast<const float2*>(bias + cb);
            #pragma unroll
            for (int hrow = 0; hrow < 2; hrow++) {
                int row = r0 + hrow * 8;
                float v0 = acc[mt][nt][hrow * 2 + 0] + bb.x;
                float v1 = acc[mt][nt][hrow * 2 + 1] + bb.y;
                if (MODE == 1) {
                    v0 = 0.5f * v0 * (1.0f + erff(v0 * 0.70710678118654752f));
                    v1 = 0.5f * v1 * (1.0f + erff(v1 * 0.70710678118654752f));
                }
                if (MODE == 2) {
                    float2 r2 = *reinterpret_cast<const float2*>(res + (size_t)row * N + cb);
                    v0 += r2.x; v1 += r2.y;
                }
                float2 o; o.x = v0; o.y = v1;
                *reinterpret_cast<float2*>(C + (size_t)row * N + cb) = o;
            }
        }
    }
}

// ---------------- rel-pos bias materialization ----------------
__global__ void bias_kernel(const float* __restrict__ rel_bias) {
    int t = blockIdx.x * blockDim.x + threadIdx.x;
    if (t >= NHEAD * NL * NL) return;
    int h = t / (NL * NL);
    int r = t % (NL * NL);
    int n = r / NL, m = r % NL;
    int id = n / 49, ih = (n / 7) % 7, iw = n % 7;
    int jd = m / 49, jh = (m / 7) % 7, jw = m % 7;
    int ridx = (id - jd + 1) * 169 + (ih - jh + 6) * 13 + (iw - jw + 6);
    g_bias[t] = rel_bias[ridx * NHEAD + h];
}

// ---------------- LN1 + cyclic shift + window partition (gather) ----------
__global__ void ln1_kernel(const float* __restrict__ x,
                           const float* __restrict__ g, const float* __restrict__ b) {
    int warp = blockIdx.x * 8 + (threadIdx.x >> 5);
    int lane = threadIdx.x & 31;
    if (warp >= TOKENS) return;
    int win = warp / NL, n = warp % NL;
    int bb  = win >> 8;
    int wl  = win & 255;
    int dz = wl >> 6, hy = (wl >> 3) & 7, wx = wl & 7;
    int id = n / 49, ih = (n / 7) % 7, iw = n % 7;
    int d  = (dz * 2 + id + 1) & 7;
    int hh = hy * 7 + ih + 3; if (hh >= 56) hh -= 56;
    int ww = wx * 7 + iw + 3; if (ww >= 56) ww -= 56;
    size_t src = ((((size_t)bb * 8 + d) * 56 + hh) * 56 + ww) * CD;

    float4 v = reinterpret_cast<const float4*>(x + src)[lane];
    float s1 = v.x + v.y + v.z + v.w;
    float s2 = v.x*v.x + v.y*v.y + v.z*v.z + v.w*v.w;
    #pragma unroll
    for (int o = 16; o; o >>= 1) {
        s1 += __shfl_xor_sync(0xffffffffu, s1, o);
        s2 += __shfl_xor_sync(0xffffffffu, s2, o);
    }
    float mean = s1 * (1.0f / 128.0f);
    float var  = s2 * (1.0f / 128.0f) - mean * mean;
    float inv  = rsqrtf(var + 1e-5f);
    float4 gg = reinterpret_cast<const float4*>(g)[lane];
    float4 bv = reinterpret_cast<const float4*>(b)[lane];
    float4 o;
    o.x = (v.x - mean) * inv * gg.x + bv.x;
    o.y = (v.y - mean) * inv * gg.y + bv.y;
    o.z = (v.z - mean) * inv * gg.z + bv.z;
    o.w = (v.w - mean) * inv * gg.w + bv.w;
    reinterpret_cast<float4*>(g_xw)[(size_t)warp * 32 + lane] = o;
}

// ---------------- LN2 ----------------
__global__ void ln2_kernel(const float* __restrict__ g, const float* __restrict__ b) {
    int warp = blockIdx.x * 8 + (threadIdx.x >> 5);
    int lane = threadIdx.x & 31;
    if (warp >= TOKENS) return;
    float4 v = reinterpret_cast<const float4*>(g_x2)[(size_t)warp * 32 + lane];
    float s1 = v.x + v.y + v.z + v.w;
    float s2 = v.x*v.x + v.y*v.y + v.z*v.z + v.w*v.w;
    #pragma unroll
    for (int o = 16; o; o >>= 1) {
        s1 += __shfl_xor_sync(0xffffffffu, s1, o);
        s2 += __shfl_xor_sync(0xffffffffu, s2, o);
    }
    float mean = s1 * (1.0f / 128.0f);
    float var  = s2 * (1.0f / 128.0f) - mean * mean;
    float inv  = rsqrtf(var + 1e-5f);
    float4 gg = reinterpret_cast<const float4*>(g)[lane];
    float4 bv = reinterpret_cast<const float4*>(b)[lane];
    float4 o;
    o.x = (v.x - mean) * inv * gg.x + bv.x;
    o.y = (v.y - mean) * inv * gg.y + bv.y;
    o.z = (v.z - mean) * inv * gg.z + bv.z;
    o.w = (v.w - mean) * inv * gg.w + bv.w;
    reinterpret_cast<float4*>(g_y)[(size_t)warp * 32 + lane] = o;
}

// ---------------- tensor-core windowed attention ----------------
// one block per (window, head), 256 threads (8 warps); warps 0-6 own m16-tiles
__global__ void __launch_bounds__(256, 2)
attn_tc(const float* __restrict__ mask) {
    extern __shared__ float smf[];
    float* Qs = smf;                     // [112][32] swizzled
    float* Ks = Qs + 112 * 32;           // [104][32] swizzled
    float* Vs = Ks + 104 * 32;           // [104][32] swizzled
    float* Ss = Vs + 104 * 32;           // [112][108]
    int win = blockIdx.x, h = blockIdx.y;
    int tid = threadIdx.x, wid = tid >> 5, lane = tid & 31;
    int g = lane >> 2, cc = lane & 3;

    // zero K/V pad rows 98..103 (avoid NaN pollution in padded mma)
    if (tid < 192) {
        int r = 98 + tid / 32, c = tid & 31;
        Vs[r * 32 + c] = 0.0f;
        Ks[r * 32 + c] = 0.0f;
    }
    // load q,k,v for this head (cvt to tf32 at store)
    const float* base = g_qkv + (size_t)win * NL * 384 + h * 32;
    for (int e = tid; e < 98 * 24; e += 256) {
        int tok = e / 24, p = e % 24;
        int which = p >> 3, c4 = p & 7;
        float4 v = *reinterpret_cast<const float4*>(base + (size_t)tok * 384 + which * 128 + c4 * 4);
        if (which == 0) {
            const float sc = 0.17677669529663689f;  // 1/sqrt(32)
            v.x *= sc; v.y *= sc; v.z *= sc; v.w *= sc;
        }
        float4 t;
        t.x = tf32r(v.x); t.y = tf32r(v.y); t.z = tf32r(v.z); t.w = tf32r(v.w);
        int col = (c4 * 4) ^ ((tok & 7) * 4);
        float* dst = (which == 0 ? Qs : which == 1 ? Ks : Vs) + tok * 32 + col;
        *reinterpret_cast<float4*>(dst) = t;
    }
    __syncthreads();

    // ---- S = Q K^T : warp wid -> m-tile wid (7 tiles) ----
    if (wid < 7) {
        int m0 = wid * 16;
        uint32_t aq[4][4];
        #pragma unroll
        for (int kc = 0; kc < 4; kc++) {
            int col0 = (kc * 8 + cc)     ^ (g * 4);
            int col1 = (kc * 8 + cc + 4) ^ (g * 4);
            aq[kc][0] = __float_as_uint(Qs[(m0 + g)     * 32 + col0]);
            aq[kc][1] = __float_as_uint(Qs[(m0 + g + 8) * 32 + col0]);
            aq[kc][2] = __float_as_uint(Qs[(m0 + g)     * 32 + col1]);
            aq[kc][3] = __float_as_uint(Qs[(m0 + g + 8) * 32 + col1]);
        }
        #pragma unroll 1
        for (int nt = 0; nt < 13; nt++) {
            float sacc[4] = {0.f, 0.f, 0.f, 0.f};
            int nr = nt * 8 + g;
            #pragma unroll
            for (int kc = 0; kc < 4; kc++) {
                int col0 = (kc * 8 + cc)     ^ (g * 4);
                int col1 = (kc * 8 + cc + 4) ^ (g * 4);
                uint32_t b0 = __float_as_uint(Ks[nr * 32 + col0]);
                uint32_t b1 = __float_as_uint(Ks[nr * 32 + col1]);
                mma_tf32(sacc, aq[kc][0], aq[kc][1], aq[kc][2], aq[kc][3], b0, b1);
            }
            float2 lo; lo.x = sacc[0]; lo.y = sacc[1];
            float2 hi; hi.x = sacc[2]; hi.y = sacc[3];
            *reinterpret_cast<float2*>(&Ss[(m0 + g)     * AT_PITCH + nt * 8 + 2 * cc]) = lo;
            *reinterpret_cast<float2*>(&Ss[(m0 + g + 8) * AT_PITCH + nt * 8 + 2 * cc]) = hi;
        }
    }
    __syncthreads();

    // ---- softmax rows (bias + mask added here), output as tf32 ----
    {
        const float* mrow = mask + (size_t)(win & 255) * (NL * NL);
        const float* brow = g_bias + (size_t)h * (NL * NL);
        for (int n = wid; n < NL; n += 8) {
            float* srow = Ss + n * AT_PITCH;
            int rb = n * NL;
            float v0 = srow[lane]      + __ldg(brow + rb + lane)      + __ldg(mrow + rb + lane);
            float v1 = srow[lane + 32] + __ldg(brow + rb + lane + 32) + __ldg(mrow + rb + lane + 32);
            float v2 = srow[lane + 64] + __ldg(brow + rb + lane + 64) + __ldg(mrow + rb + lane + 64);
            int c3 = lane + 96;
            bool has3 = (c3 < NL);
            float v3 = has3 ? (srow[c3] + __ldg(brow + rb + c3) + __ldg(mrow + rb + c3)) : -3.0e38f;
            float mx = fmaxf(fmaxf(v0, v1), fmaxf(v2, v3));
            #pragma unroll
            for (int o = 16; o; o >>= 1) mx = fmaxf(mx, __shfl_xor_sync(0xffffffffu, mx, o));
            v0 = __expf(v0 - mx); v1 = __expf(v1 - mx); v2 = __expf(v2 - mx);
            v3 = has3 ? __expf(v3 - mx) : 0.0f;
            float sum = v0 + v1 + v2 + v3;
            #pragma unroll
            for (int o = 16; o; o >>= 1) sum += __shfl_xor_sync(0xffffffffu, sum, o);
            float r = 1.0f / sum;
            srow[lane]      = tf32r(v0 * r);
            srow[lane + 32] = tf32r(v1 * r);
            srow[lane + 64] = tf32r(v2 * r);
            if (c3 < 104) srow[c3] = has3 ? tf32r(v3 * r) : 0.0f;  // zero pad cols 98..103
        }
    }
    __syncthreads();

    // ---- O = P V : warp wid -> m-tile wid ----
    if (wid < 7) {
        int m0 = wid * 16;
        float oacc[4][4];
        #pragma unroll
        for (int nt = 0; nt < 4; nt++)
            #pragma unroll
            for (int t = 0; t < 4; t++) oacc[nt][t] = 0.0f;
        #pragma unroll 1
        for (int kc = 0; kc < 13; kc++) {
            int k0 = kc * 8;
            uint32_t a0 = __float_as_uint(Ss[(m0 + g)     * AT_PITCH + k0 + cc]);
            uint32_t a1 = __float_as_uint(Ss[(m0 + g + 8) * AT_PITCH + k0 + cc]);
            uint32_t a2 = __float_as_uint(Ss[(m0 + g)     * AT_PITCH + k0 + cc + 4]);
            uint32_t a3 = __float_as_uint(Ss[(m0 + g + 8) * AT_PITCH + k0 + cc + 4]);
            #pragma unroll
            for (int nt = 0; nt < 4; nt++) {
                int col0 = (nt * 8 + g) ^ (4 * cc);
                int col1 = (nt * 8 + g) ^ (4 * (cc + 4));
                uint32_t b0 = __float_as_uint(Vs[(k0 + cc)     * 32 + col0]);
                uint32_t b1 = __float_as_uint(Vs[(k0 + cc + 4) * 32 + col1]);
                mma_tf32(oacc[nt], a0, a1, a2, a3, b0, b1);
            }
        }
        float* ob = g_attn + (size_t)win * NL * CD + h * 32;
        int r0 = m0 + g, r1 = m0 + g + 8;
        #pragma unroll
        for (int nt = 0; nt < 4; nt++) {
            int cb = nt * 8 + 2 * cc;
            if (r0 < NL) {
                float2 o; o.x = oacc[nt][0]; o.y = oacc[nt][1];
                *reinterpret_cast<float2*>(ob + (size_t)r0 * CD + cb) = o;
            }
            if (r1 < NL) {
                float2 o; o.x = oacc[nt][2]; o.y = oacc[nt][3];
                *reinterpret_cast<float2*>(ob + (size_t)r1 * CD + cb) = o;
            }
        }
    }
}

// ---------------- window reverse + roll + residual add -> x2 --------------
__global__ void residual_kernel(const float* __restrict__ x) {
    size_t idx = (size_t)blockIdx.x * 256 + threadIdx.x;
    if (idx >= (size_t)TOKENS * 32) return;
    int t  = (int)(idx >> 5);
    int c4 = (int)(idx & 31);
    int w  = t % 56;
    int hh = (t / 56) % 56;
    int d  = (t / 3136) % 8;
    int bb = t / 25088;
    int ds = (d + 7) & 7;
    int hs = hh - 3; if (hs < 0) hs += 56;
    int ws = w  - 3; if (ws < 0) ws += 56;
    int win = bb * 256 + (ds >> 1) * 64 + (hs / 7) * 8 + (ws / 7);
    int n   = (ds & 1) * 49 + (hs % 7) * 7 + (ws % 7);
    float4 p  = reinterpret_cast<const float4*>(g_proj)[((size_t)win * NL + n) * 32 + c4];
    float4 xv = reinterpret_cast<const float4*>(x)[idx];
    float4 o;
    o.x = xv.x + p.x; o.y = xv.y + p.y; o.z = xv.z + p.z; o.w = xv.w + p.w;
    reinterpret_cast<float4*>(g_x2)[idx] = o;
}

// ---------------- launch ----------------
extern "C" void kernel_launch(void* const* d_in, const int* in_sizes, int n_in,
                              void* d_out, int out_size) {
    const float* x     = (const float*)d_in[0];
    const float* mask  = (const float*)d_in[1];
    const float* n1g   = (const float*)d_in[2];
    const float* n1b   = (const float*)d_in[3];
    const float* qkvw  = (const float*)d_in[4];
    const float* qkvb  = (const float*)d_in[5];
    const float* relb  = (const float*)d_in[6];
    const float* projw = (const float*)d_in[7];
    const float* projb = (const float*)d_in[8];
    const float* n2g   = (const float*)d_in[9];
    const float* n2b   = (const float*)d_in[10];
    const float* fc1w  = (const float*)d_in[11];
    const float* fc1b  = (const float*)d_in[12];
    const float* fc2w  = (const float*)d_in[13];
    const float* fc2b  = (const float*)d_in[14];
    float* out = (float*)d_out;

    void *p_xw, *p_qkv, *p_attn, *p_proj, *p_x2, *p_y, *p_hid;
    cudaGetSymbolAddress(&p_xw,   g_xw);
    cudaGetSymbolAddress(&p_qkv,  g_qkv);
    cudaGetSymbolAddress(&p_attn, g_attn);
    cudaGetSymbolAddress(&p_proj, g_proj);
    cudaGetSymbolAddress(&p_x2,   g_x2);
    cudaGetSymbolAddress(&p_y,    g_y);
    cudaGetSymbolAddress(&p_hid,  g_hid);

    cudaFuncSetAttribute(attn_tc, cudaFuncAttributeMaxDynamicSharedMemorySize, ATTN_SMEM);

    bias_kernel<<<(NHEAD * NL * NL + 255) / 256, 256>>>(relb);
    ln1_kernel<<<TOKENS / 8, 256>>>(x, n1g, n1b);
    mma_gemm<0><<<dim3(3, TOKENS / 128), 256>>>(
        (const float*)p_xw, qkvw, qkvb, nullptr, (float*)p_qkv, 128, 384);
    attn_tc<<<dim3(NWIN, NHEAD), 256, ATTN_SMEM>>>(mask);
    mma_gemm<0><<<dim3(1, TOKENS / 128), 256>>>(
        (const float*)p_attn, projw, projb, nullptr, (float*)p_proj, 128, 128);
    residual_kernel<<<(TOKENS * 32) / 256, 256>>>(x);
    ln2_kernel<<<TOKENS / 8, 256>>>(n2g, n2b);
    mma_gemm<1><<<dim3(4, TOKENS / 128), 256>>>(
        (const float*)p_y, fc1w, fc1b, nullptr, (float*)p_hid, 128, 512);
    mma_gemm<2><<<dim3(1, TOKENS / 128), 256>>>(
        (const float*)p_hid, fc2w, fc2b, (const float*)p_x2, out, 512, 128);
}

// round 5
// speedup vs baseline: 3.2139x; 1.2308x over previous
#include <cuda_runtime.h>
#include <math.h>
#include <stdint.h>

// ---------------- problem constants ----------------
#define TOKENS 200704          // 8*8*56*56
#define CD     128             // channels
#define NWIN   2048            // windows (8 * 4*8*8)
#define NL     98              // tokens per window
#define NHEAD  4

#define GEMM_SMEM_DB (4 * 16384)   // 64KB: As[2][128][32] + Bs[2][128][32] fp32

// weight cvt offsets (floats)
#define W_QKV  0
#define W_PROJ 49152
#define W_FC1  65536
#define W_FC2  131072
#define W_TOT  196608

// ---------------- scratch ----------------
__device__ float g_xw  [(size_t)TOKENS * CD];
__device__ float g_qkv [(size_t)TOKENS * 3 * CD];
__device__ float g_bias[(size_t)NHEAD * NL * NL];
__device__ float g_attn[(size_t)TOKENS * CD];
__device__ float g_proj[(size_t)TOKENS * CD];
__device__ float g_x2  [(size_t)TOKENS * CD];
__device__ float g_y   [(size_t)TOKENS * CD];
__device__ float g_hid [(size_t)TOKENS * 4 * CD];
__device__ float g_wcvt[W_TOT];

// ---------------- helpers ----------------
__device__ __forceinline__ float tf32r(float v) {
    uint32_t o;
    asm("cvt.rna.tf32.f32 %0, %1;" : "=r"(o) : "f"(v));
    return __uint_as_float(o);
}
__device__ __forceinline__ void mma_tf32(float c[4],
                                         uint32_t a0, uint32_t a1, uint32_t a2, uint32_t a3,
                                         uint32_t b0, uint32_t b1) {
    asm volatile(
        "mma.sync.aligned.m16n8k8.row.col.f32.tf32.tf32.f32 "
        "{%0,%1,%2,%3}, {%4,%5,%6,%7}, {%8,%9}, {%0,%1,%2,%3};\n"
        : "+f"(c[0]), "+f"(c[1]), "+f"(c[2]), "+f"(c[3])
        : "r"(a0), "r"(a1), "r"(a2), "r"(a3), "r"(b0), "r"(b1));
}
__device__ __forceinline__ uint32_t smem_u32(const void* p) {
    uint32_t a;
    asm("{ .reg .u64 t; cvta.to.shared.u64 t, %1; cvt.u32.u64 %0, t; }" : "=r"(a) : "l"(p));
    return a;
}
#define CP16(dst, src) \
    asm volatile("cp.async.cg.shared.global [%0], [%1], 16;\n" :: "r"(dst), "l"(src))

// ---------------- weight tf32 pre-conversion ----------------
__global__ void cvt_kernel(const float* __restrict__ in, float* __restrict__ out, int n) {
    int i = blockIdx.x * 256 + threadIdx.x;
    if (i < n) out[i] = tf32r(in[i]);
}

// ============ double-buffered cp.async tf32 GEMM ============
// A and W MUST already be tf32-rounded. C = A(MxK) @ W(NxK)^T + bias [+gelu|+res]
template<int MODE>
__global__ void __launch_bounds__(256, 2)
mma_gemm(const float* __restrict__ A, const float* __restrict__ W,
         const float* __restrict__ bias, const float* __restrict__ res,
         float* __restrict__ C, int K, int N) {
    extern __shared__ float gsm[];          // As[2][128][32] | Bs[2][128][32]
    uint32_t sb = smem_u32(gsm);
    int tid = threadIdx.x;
    int wid = tid >> 5, lane = tid & 31;
    int g = lane >> 2, cc = lane & 3;
    int m0 = blockIdx.y * 128, n0 = blockIdx.x * 128;
    int wm = wid & 1, wn = wid >> 1;

    float acc[4][4][4];
    #pragma unroll
    for (int i = 0; i < 4; i++)
        #pragma unroll
        for (int j = 0; j < 4; j++)
            #pragma unroll
            for (int t = 0; t < 4; t++) acc[i][j][t] = 0.0f;

    int r_ld = tid >> 3, c4_ld = tid & 7;           // thread's base row/col4
    uint32_t soff_base = ((uint32_t)r_ld * 32 + (((uint32_t)c4_ld * 4) ^ ((r_ld & 7) * 4))) * 4;

    int nc = K >> 5;
    // issue chunk kc into buffer buf
    auto issue = [&](int kc, int buf) {
        int k0 = kc * 32;
        #pragma unroll
        for (int i = 0; i < 4; i++) {
            int r = r_ld + i * 32;
            uint32_t soff = soff_base + (uint32_t)i * 32 * 32 * 4;
            const float* srcA = A + (size_t)(m0 + r) * K + k0 + c4_ld * 4;
            CP16(sb + buf * 16384 + soff, srcA);
            const float* srcB = W + (size_t)(n0 + r) * K + k0 + c4_ld * 4;
            CP16(sb + 32768 + buf * 16384 + soff, srcB);
        }
        asm volatile("cp.async.commit_group;\n" ::: "memory");
    };

    issue(0, 0);
    for (int kc = 0; kc < nc; kc++) {
        if (kc + 1 < nc) {
            issue(kc + 1, (kc + 1) & 1);
            asm volatile("cp.async.wait_group 1;\n" ::: "memory");
        } else {
            asm volatile("cp.async.wait_group 0;\n" ::: "memory");
        }
        __syncthreads();
        const float* Ab = gsm + (kc & 1) * 4096;
        const float* Bb = gsm + 8192 + (kc & 1) * 4096;
        #pragma unroll
        for (int ks = 0; ks < 4; ks++) {
            int k0 = ks * 8;
            int sw = g * 4;
            uint32_t af[4][4];
            #pragma unroll
            for (int mt = 0; mt < 4; mt++) {
                int rb = wm * 64 + mt * 16 + g;
                af[mt][0] = __float_as_uint(Ab[rb * 32       + ((k0 + cc)     ^ sw)]);
                af[mt][1] = __float_as_uint(Ab[(rb + 8) * 32 + ((k0 + cc)     ^ sw)]);
                af[mt][2] = __float_as_uint(Ab[rb * 32       + ((k0 + cc + 4) ^ sw)]);
                af[mt][3] = __float_as_uint(Ab[(rb + 8) * 32 + ((k0 + cc + 4) ^ sw)]);
            }
            uint32_t bf[4][2];
            #pragma unroll
            for (int nt = 0; nt < 4; nt++) {
                int nb = wn * 32 + nt * 8 + g;
                bf[nt][0] = __float_as_uint(Bb[nb * 32 + ((k0 + cc)     ^ sw)]);
                bf[nt][1] = __float_as_uint(Bb[nb * 32 + ((k0 + cc + 4) ^ sw)]);
            }
            #pragma unroll
            for (int mt = 0; mt < 4; mt++)
                #pragma unroll
                for (int nt = 0; nt < 4; nt++)
                    mma_tf32(acc[mt][nt], af[mt][0], af[mt][1], af[mt][2], af[mt][3],
                             bf[nt][0], bf[nt][1]);
        }
        __syncthreads();
    }

    #pragma unroll
    for (int mt = 0; mt < 4; mt++) {
        int r0 = m0 + wm * 64 + mt * 16 + g;
        #pragma unroll
        for (int nt = 0; nt < 4; nt++) {
            int cb = n0 + wn * 32 + nt * 8 + cc * 2;
            float2 bb = *reinterpret_cast<const float2*>(bias + cb);
            #pragma unroll
            for (int hrow = 0; hrow < 2; hrow++) {
                int row = r0 + hrow * 8;
                float v0 = acc[mt][nt][hrow * 2 + 0] + bb.x;
                float v1 = acc[mt][nt][hrow * 2 + 1] + bb.y;
                if (MODE == 1) {
                    v0 = tf32r(0.5f * v0 * (1.0f + erff(v0 * 0.70710678118654752f)));
                    v1 = tf32r(0.5f * v1 * (1.0f + erff(v1 * 0.70710678118654752f)));
                }
                if (MODE == 2) {
                    float2 r2 = *reinterpret_cast<const float2*>(res + (size_t)row * N + cb);
                    v0 += r2.x; v1 += r2.y;
                }
                float2 o; o.x = v0; o.y = v1;
                *reinterpret_cast<float2*>(C + (size_t)row * N + cb) = o;
            }
        }
    }
}

// ---------------- rel-pos bias materialization ----------------
__global__ void bias_kernel(const float* __restrict__ rel_bias) {
    int t = blockIdx.x * blockDim.x + threadIdx.x;
    if (t >= NHEAD * NL * NL) return;
    int h = t / (NL * NL);
    int r = t % (NL * NL);
    int n = r / NL, m = r % NL;
    int id = n / 49, ih = (n / 7) % 7, iw = n % 7;
    int jd = m / 49, jh = (m / 7) % 7, jw = m % 7;
    int ridx = (id - jd + 1) * 169 + (ih - jh + 6) * 13 + (iw - jw + 6);
    g_bias[t] = rel_bias[ridx * NHEAD + h];
}

// ---------------- LN1 + shift + window partition (tf32 out) ----------------
__global__ void ln1_kernel(const float* __restrict__ x,
                           const float* __restrict__ g, const float* __restrict__ b) {
    int warp = blockIdx.x * 8 + (threadIdx.x >> 5);
    int lane = threadIdx.x & 31;
    if (warp >= TOKENS) return;
    int win = warp / NL, n = warp % NL;
    int bb  = win >> 8;
    int wl  = win & 255;
    int dz = wl >> 6, hy = (wl >> 3) & 7, wx = wl & 7;
    int id = n / 49, ih = (n / 7) % 7, iw = n % 7;
    int d  = (dz * 2 + id + 1) & 7;
    int hh = hy * 7 + ih + 3; if (hh >= 56) hh -= 56;
    int ww = wx * 7 + iw + 3; if (ww >= 56) ww -= 56;
    size_t src = ((((size_t)bb * 8 + d) * 56 + hh) * 56 + ww) * CD;

    float4 v = reinterpret_cast<const float4*>(x + src)[lane];
    float s1 = v.x + v.y + v.z + v.w;
    float s2 = v.x*v.x + v.y*v.y + v.z*v.z + v.w*v.w;
    #pragma unroll
    for (int o = 16; o; o >>= 1) {
        s1 += __shfl_xor_sync(0xffffffffu, s1, o);
        s2 += __shfl_xor_sync(0xffffffffu, s2, o);
    }
    float mean = s1 * (1.0f / 128.0f);
    float var  = s2 * (1.0f / 128.0f) - mean * mean;
    float inv  = rsqrtf(var + 1e-5f);
    float4 gg = reinterpret_cast<const float4*>(g)[lane];
    float4 bv = reinterpret_cast<const float4*>(b)[lane];
    float4 o;
    o.x = tf32r((v.x - mean) * inv * gg.x + bv.x);
    o.y = tf32r((v.y - mean) * inv * gg.y + bv.y);
    o.z = tf32r((v.z - mean) * inv * gg.z + bv.z);
    o.w = tf32r((v.w - mean) * inv * gg.w + bv.w);
    reinterpret_cast<float4*>(g_xw)[(size_t)warp * 32 + lane] = o;
}

// ---------------- LN2 (tf32 out) ----------------
__global__ void ln2_kernel(const float* __restrict__ g, const float* __restrict__ b) {
    int warp = blockIdx.x * 8 + (threadIdx.x >> 5);
    int lane = threadIdx.x & 31;
    if (warp >= TOKENS) return;
    float4 v = reinterpret_cast<const float4*>(g_x2)[(size_t)warp * 32 + lane];
    float s1 = v.x + v.y + v.z + v.w;
    float s2 = v.x*v.x + v.y*v.y + v.z*v.z + v.w*v.w;
    #pragma unroll
    for (int o = 16; o; o >>= 1) {
        s1 += __shfl_xor_sync(0xffffffffu, s1, o);
        s2 += __shfl_xor_sync(0xffffffffu, s2, o);
    }
    float mean = s1 * (1.0f / 128.0f);
    float var  = s2 * (1.0f / 128.0f) - mean * mean;
    float inv  = rsqrtf(var + 1e-5f);
    float4 gg = reinterpret_cast<const float4*>(g)[lane];
    float4 bv = reinterpret_cast<const float4*>(b)[lane];
    float4 o;
    o.x = tf32r((v.x - mean) * inv * gg.x + bv.x);
    o.y = tf32r((v.y - mean) * inv * gg.y + bv.y);
    o.z = tf32r((v.z - mean) * inv * gg.z + bv.z);
    o.w = tf32r((v.w - mean) * inv * gg.w + bv.w);
    reinterpret_cast<float4*>(g_y)[(size_t)warp * 32 + lane] = o;
}

// ---------------- flash-style register attention ----------------
// one block per (window, head); 224 threads = 7 warps; warp w owns rows [16w,16w+16)
// S lives entirely in registers; softmax via quad shuffles; P repacked by shuffle.
__global__ void __launch_bounds__(224, 2)
attn_flash(const float* __restrict__ mask) {
    __shared__ float Qs[112 * 32];
    __shared__ float Ks[104 * 32];
    __shared__ float Vs[104 * 32];
    int win = blockIdx.x, h = blockIdx.y;
    int tid = threadIdx.x, wid = tid >> 5, lane = tid & 31;
    int g = lane >> 2, cc = lane & 3;

    // zero pad rows
    for (int i = tid; i < 14 * 32; i += 224) Qs[98 * 32 + i] = 0.0f;
    if (tid < 192) { Ks[98 * 32 + tid] = 0.0f; Vs[98 * 32 + tid] = 0.0f; }
    // load Q/K/V for this head, swizzled, tf32-rounded (Q pre-scaled)
    const float* base = g_qkv + (size_t)win * NL * 384 + h * 32;
    for (int e = tid; e < 98 * 24; e += 224) {
        int tok = e / 24, p = e - tok * 24;
        int which = p >> 3, c4 = p & 7;
        float4 v = *reinterpret_cast<const float4*>(base + (size_t)tok * 384 + which * 128 + c4 * 4);
        if (which == 0) {
            const float sc = 0.17677669529663689f;
            v.x *= sc; v.y *= sc; v.z *= sc; v.w *= sc;
        }
        float4 t;
        t.x = tf32r(v.x); t.y = tf32r(v.y); t.z = tf32r(v.z); t.w = tf32r(v.w);
        int col = (c4 * 4) ^ ((tok & 7) * 4);
        float* dst = (which == 0 ? Qs : which == 1 ? Ks : Vs) + tok * 32 + col;
        *reinterpret_cast<float4*>(dst) = t;
    }
    __syncthreads();

    int m0 = wid * 16;
    int r0 = m0 + g, r1 = m0 + g + 8;
    int sw = g * 4;

    // Q fragments
    uint32_t aq[4][4];
    #pragma unroll
    for (int kc = 0; kc < 4; kc++) {
        int col0 = (kc * 8 + cc) ^ sw;
        int col1 = (kc * 8 + cc + 4) ^ sw;
        aq[kc][0] = __float_as_uint(Qs[r0 * 32 + col0]);
        aq[kc][1] = __float_as_uint(Qs[r1 * 32 + col0]);
        aq[kc][2] = __float_as_uint(Qs[r0 * 32 + col1]);
        aq[kc][3] = __float_as_uint(Qs[r1 * 32 + col1]);
    }

    // S = Q K^T, all 13 n-tiles in registers
    float sacc[13][4];
    #pragma unroll
    for (int nt = 0; nt < 13; nt++) {
        float s[4] = {0.f, 0.f, 0.f, 0.f};
        int nr = nt * 8 + g;
        #pragma unroll
        for (int kc = 0; kc < 4; kc++) {
            int col0 = (kc * 8 + cc) ^ sw;
            int col1 = (kc * 8 + cc + 4) ^ sw;
            uint32_t b0 = __float_as_uint(Ks[nr * 32 + col0]);
            uint32_t b1 = __float_as_uint(Ks[nr * 32 + col1]);
            mma_tf32(s, aq[kc][0], aq[kc][1], aq[kc][2], aq[kc][3], b0, b1);
        }
        sacc[nt][0] = s[0]; sacc[nt][1] = s[1]; sacc[nt][2] = s[2]; sacc[nt][3] = s[3];
    }

    // bias + mask (clamp dead rows to stay in-bounds; kill cols >= 98)
    {
        const float* bm = g_bias + (size_t)h * (NL * NL);
        const float* mk = mask + (size_t)(win & 255) * (NL * NL);
        int rc0 = (r0 < 98 ? r0 : 97) * 98;
        int rc1 = (r1 < 98 ? r1 : 97) * 98;
        #pragma unroll
        for (int nt = 0; nt < 13; nt++) {
            int col = nt * 8 + 2 * cc;
            if (col < 98) {
                sacc[nt][0] += __ldg(bm + rc0 + col) + __ldg(mk + rc0 + col);
                sacc[nt][2] += __ldg(bm + rc1 + col) + __ldg(mk + rc1 + col);
            } else { sacc[nt][0] = -1.0e38f; sacc[nt][2] = -1.0e38f; }
            if (col + 1 < 98) {
                sacc[nt][1] += __ldg(bm + rc0 + col + 1) + __ldg(mk + rc0 + col + 1);
                sacc[nt][3] += __ldg(bm + rc1 + col + 1) + __ldg(mk + rc1 + col + 1);
            } else { sacc[nt][1] = -1.0e38f; sacc[nt][3] = -1.0e38f; }
        }
    }

    // softmax over rows r0 (slots 0,1) and r1 (slots 2,3), spread across quad
    float mx0 = -1.0e38f, mx1 = -1.0e38f;
    #pragma unroll
    for (int nt = 0; nt < 13; nt++) {
        mx0 = fmaxf(mx0, fmaxf(sacc[nt][0], sacc[nt][1]));
        mx1 = fmaxf(mx1, fmaxf(sacc[nt][2], sacc[nt][3]));
    }
    mx0 = fmaxf(mx0, __shfl_xor_sync(0xffffffffu, mx0, 1));
    mx0 = fmaxf(mx0, __shfl_xor_sync(0xffffffffu, mx0, 2));
    mx1 = fmaxf(mx1, __shfl_xor_sync(0xffffffffu, mx1, 1));
    mx1 = fmaxf(mx1, __shfl_xor_sync(0xffffffffu, mx1, 2));
    float sm0 = 0.f, sm1 = 0.f;
    #pragma unroll
    for (int nt = 0; nt < 13; nt++) {
        sacc[nt][0] = __expf(sacc[nt][0] - mx0);
        sacc[nt][1] = __expf(sacc[nt][1] - mx0);
        sacc[nt][2] = __expf(sacc[nt][2] - mx1);
        sacc[nt][3] = __expf(sacc[nt][3] - mx1);
        sm0 += sacc[nt][0] + sacc[nt][1];
        sm1 += sacc[nt][2] + sacc[nt][3];
    }
    sm0 += __shfl_xor_sync(0xffffffffu, sm0, 1);
    sm0 += __shfl_xor_sync(0xffffffffu, sm0, 2);
    sm1 += __shfl_xor_sync(0xffffffffu, sm1, 1);
    sm1 += __shfl_xor_sync(0xffffffffu, sm1, 2);
    float iv0 = 1.0f / sm0, iv1 = 1.0f / sm1;
    #pragma unroll
    for (int nt = 0; nt < 13; nt++) {
        sacc[nt][0] = tf32r(sacc[nt][0] * iv0);
        sacc[nt][1] = tf32r(sacc[nt][1] * iv0);
        sacc[nt][2] = tf32r(sacc[nt][2] * iv1);
        sacc[nt][3] = tf32r(sacc[nt][3] * iv1);
    }

    // O = P V : repack P C-frag -> A-frag via quad shuffles, mma against V
    float oacc[4][4];
    #pragma unroll
    for (int vt = 0; vt < 4; vt++)
        #pragma unroll
        for (int t = 0; t < 4; t++) oacc[vt][t] = 0.0f;
    int qb = lane & ~3;
    int src0 = qb + (cc >> 1);
    bool odd = (cc & 1);
    #pragma unroll
    for (int kc = 0; kc < 13; kc++) {
        float p0 = sacc[kc][0], p1 = sacc[kc][1], p2 = sacc[kc][2], p3 = sacc[kc][3];
        float t0 = __shfl_sync(0xffffffffu, p0, src0);
        float t1 = __shfl_sync(0xffffffffu, p1, src0);
        float u0 = __shfl_sync(0xffffffffu, p0, src0 + 2);
        float u1 = __shfl_sync(0xffffffffu, p1, src0 + 2);
        float t2 = __shfl_sync(0xffffffffu, p2, src0);
        float t3 = __shfl_sync(0xffffffffu, p3, src0);
        float u2 = __shfl_sync(0xffffffffu, p2, src0 + 2);
        float u3 = __shfl_sync(0xffffffffu, p3, src0 + 2);
        uint32_t a0 = __float_as_uint(odd ? t1 : t0);
        uint32_t a2 = __float_as_uint(odd ? u1 : u0);
        uint32_t a1 = __float_as_uint(odd ? t3 : t2);
        uint32_t a3 = __float_as_uint(odd ? u3 : u2);
        int k0 = kc * 8;
        #pragma unroll
        for (int vt = 0; vt < 4; vt++) {
            uint32_t b0 = __float_as_uint(Vs[(k0 + cc) * 32     + ((vt * 8 + g) ^ (cc * 4))]);
            uint32_t b1 = __float_as_uint(Vs[(k0 + cc + 4) * 32 + ((vt * 8 + g) ^ (cc * 4 + 16))]);
            mma_tf32(oacc[vt], a0, a1, a2, a3, b0, b1);
        }
    }

    float* ob = g_attn + (size_t)win * NL * CD + h * 32;
    #pragma unroll
    for (int vt = 0; vt < 4; vt++) {
        int cb = vt * 8 + 2 * cc;
        if (r0 < NL) {
            float2 o; o.x = tf32r(oacc[vt][0]); o.y = tf32r(oacc[vt][1]);
            *reinterpret_cast<float2*>(ob + (size_t)r0 * CD + cb) = o;
        }
        if (r1 < NL) {
            float2 o; o.x = tf32r(oacc[vt][2]); o.y = tf32r(oacc[vt][3]);
            *reinterpret_cast<float2*>(ob + (size_t)r1 * CD + cb) = o;
        }
    }
}

// ---------------- window reverse + roll + residual -> x2 ----------------
__global__ void residual_kernel(const float* __restrict__ x) {
    size_t idx = (size_t)blockIdx.x * 256 + threadIdx.x;
    if (idx >= (size_t)TOKENS * 32) return;
    int t  = (int)(idx >> 5);
    int c4 = (int)(idx & 31);
    int w  = t % 56;
    int hh = (t / 56) % 56;
    int d  = (t / 3136) % 8;
    int bb = t / 25088;
    int ds = (d + 7) & 7;
    int hs = hh - 3; if (hs < 0) hs += 56;
    int ws = w  - 3; if (ws < 0) ws += 56;
    int win = bb * 256 + (ds >> 1) * 64 + (hs / 7) * 8 + (ws / 7);
    int n   = (ds & 1) * 49 + (hs % 7) * 7 + (ws % 7);
    float4 p  = reinterpret_cast<const float4*>(g_proj)[((size_t)win * NL + n) * 32 + c4];
    float4 xv = reinterpret_cast<const float4*>(x)[idx];
    float4 o;
    o.x = xv.x + p.x; o.y = xv.y + p.y; o.z = xv.z + p.z; o.w = xv.w + p.w;
    reinterpret_cast<float4*>(g_x2)[idx] = o;
}

// ---------------- launch ----------------
extern "C" void kernel_launch(void* const* d_in, const int* in_sizes, int n_in,
                              void* d_out, int out_size) {
    const float* x     = (const float*)d_in[0];
    const float* mask  = (const float*)d_in[1];
    const float* n1g   = (const float*)d_in[2];
    const float* n1b   = (const float*)d_in[3];
    const float* qkvw  = (const float*)d_in[4];
    const float* qkvb  = (const float*)d_in[5];
    const float* relb  = (const float*)d_in[6];
    const float* projw = (const float*)d_in[7];
    const float* projb = (const float*)d_in[8];
    const float* n2g   = (const float*)d_in[9];
    const float* n2b   = (const float*)d_in[10];
    const float* fc1w  = (const float*)d_in[11];
    const float* fc1b  = (const float*)d_in[12];
    const float* fc2w  = (const float*)d_in[13];
    const float* fc2b  = (const float*)d_in[14];
    float* out = (float*)d_out;

    void *p_xw, *p_qkv, *p_attn, *p_proj, *p_x2, *p_y, *p_hid, *p_w;
    cudaGetSymbolAddress(&p_xw,   g_xw);
    cudaGetSymbolAddress(&p_qkv,  g_qkv);
    cudaGetSymbolAddress(&p_attn, g_attn);
    cudaGetSymbolAddress(&p_proj, g_proj);
    cudaGetSymbolAddress(&p_x2,   g_x2);
    cudaGetSymbolAddress(&p_y,    g_y);
    cudaGetSymbolAddress(&p_hid,  g_hid);
    cudaGetSymbolAddress(&p_w,    g_wcvt);
    float* wc = (float*)p_w;

    cudaFuncSetAttribute(mma_gemm<0>, cudaFuncAttributeMaxDynamicSharedMemorySize, GEMM_SMEM_DB);
    cudaFuncSetAttribute(mma_gemm<1>, cudaFuncAttributeMaxDynamicSharedMemorySize, GEMM_SMEM_DB);
    cudaFuncSetAttribute(mma_gemm<2>, cudaFuncAttributeMaxDynamicSharedMemorySize, GEMM_SMEM_DB);

    // weight pre-conversion + bias table
    cvt_kernel<<<(49152 + 255) / 256, 256>>>(qkvw, wc + W_QKV, 49152);
    cvt_kernel<<<(16384 + 255) / 256, 256>>>(projw, wc + W_PROJ, 16384);
    cvt_kernel<<<(65536 + 255) / 256, 256>>>(fc1w, wc + W_FC1, 65536);
    cvt_kernel<<<(65536 + 255) / 256, 256>>>(fc2w, wc + W_FC2, 65536);
    bias_kernel<<<(NHEAD * NL * NL + 255) / 256, 256>>>(relb);

    ln1_kernel<<<TOKENS / 8, 256>>>(x, n1g, n1b);
    mma_gemm<0><<<dim3(3, TOKENS / 128), 256, GEMM_SMEM_DB>>>(
        (const float*)p_xw, wc + W_QKV, qkvb, nullptr, (float*)p_qkv, 128, 384);
    attn_flash<<<dim3(NWIN, NHEAD), 224>>>(mask);
    mma_gemm<0><<<dim3(1, TOKENS / 128), 256, GEMM_SMEM_DB>>>(
        (const float*)p_attn, wc + W_PROJ, projb, nullptr, (float*)p_proj, 128, 128);
    residual_kernel<<<(TOKENS * 32) / 256, 256>>>(x);
    ln2_kernel<<<TOKENS / 8, 256>>>(n2g, n2b);
    mma_gemm<1><<<dim3(4, TOKENS / 128), 256, GEMM_SMEM_DB>>>(
        (const float*)p_y, wc + W_FC1, fc1b, nullptr, (float*)p_hid, 128, 512);
    mma_gemm<2><<<dim3(1, TOKENS / 128), 256, GEMM_SMEM_DB>>>(
        (const float*)p_hid, wc + W_FC2, fc2b, (const float*)p_x2, out, 512, 128);
}